// round 12
// baseline (speedup 1.0000x reference)
#include <cuda_runtime.h>
#include <math.h>

// Problem: B=128, T=128, K=8, H=3, HID=256, OUT=2
// grid = 512: bb = blk>>2 (batch), r0 = (blk&3)*32 (row window)
// block = 256 threads, 4 CTAs/SM (launch_bounds(256,4) -> 64 regs, no spills
// by design: phase-2 tile = 16 packed accumulators)
#define TTK 128
#define NROWS 32
#define XP  36     // xst pad  (36*4 % 16 == 0 -> LDS.128 legal)
#define HP  36     // hs_t pad
#define H2P 260    // hs2 pad  (260*4 % 16 == 0 -> float4 rows)
#define XST_FLOATS (32 * XP)            // 1152
#define BUF_FLOATS (256 * HP)           // 9216
#define SMEM_FLOATS (XST_FLOATS + BUF_FLOATS)   // 10368
#define SMEM_BYTES  (SMEM_FLOATS * 4)           // 41472
// buf sub-offsets (attention view)
#define SK_OFF 0
#define SV_OFF 3072
#define WS_OFF 6144
#define PS_OFF 6720
#define PO_OFF 6912

typedef unsigned long long ull;

__device__ __forceinline__ ull pack2(float lo, float hi) {
    ull r; asm("mov.b64 %0,{%1,%2};" : "=l"(r) : "f"(lo), "f"(hi)); return r;
}
__device__ __forceinline__ void unpack2(ull v, float& lo, float& hi) {
    asm("mov.b64 {%0,%1},%2;" : "=f"(lo), "=f"(hi) : "l"(v));
}
__device__ __forceinline__ ull ffma2(ull a, ull b, ull c) {
    ull d; asm("fma.rn.f32x2 %0,%1,%2,%3;" : "=l"(d) : "l"(a), "l"(b), "l"(c));
    return d;
}
__device__ __forceinline__ ull mul2(ull a, ull b) {
    ull d; asm("mul.rn.f32x2 %0,%1,%2;" : "=l"(d) : "l"(a), "l"(b)); return d;
}

// Accurate fp32 tanh (fast-math tanhf -> tanh.approx.f32, ~1e-4 ABS error;
// outputs are ~1e-3 scale -> need controlled error).
__device__ __forceinline__ float tanh_acc(float x) {
    float ax = fabsf(x);
    if (ax < 0.25f) {
        float x2 = x * x;
        float p = fmaf(x2, -0.05396825396825397f, 0.13333333333333333f);
        p = fmaf(x2, p, -0.3333333333333333f);
        p = fmaf(x2, p, 1.0f);
        return x * p;
    }
    float t = __expf(2.0f * fminf(ax, 44.0f));
    float r = (t - 1.0f) / (t + 1.0f);
    return copysignf(r, x);
}

__global__ __launch_bounds__(256, 4) void actor_kernel(
    const float* __restrict__ state, const float* __restrict__ noise,
    const float* __restrict__ Wq, const float* __restrict__ Wk,
    const float* __restrict__ Wv,
    const float* __restrict__ W1, const float* __restrict__ b1,
    const float* __restrict__ W2, const float* __restrict__ b2,
    const float* __restrict__ Wmu, const float* __restrict__ bmu,
    const float* __restrict__ Wls, const float* __restrict__ bls,
    float* __restrict__ out_action, float* __restrict__ out_logp) {
    extern __shared__ float sm[];
    float* xst = sm;                 // [32][XP] x-features transposed
    float* buf = sm + XST_FLOATS;    // union: attn views | hs_t [256][HP] | hs2 [32][H2P]
    float* sk = buf + SK_OFF;        // [3][128][8]
    float* sv = buf + SV_OFF;        // [3][128][8]
    float* ws = buf + WS_OFF;        // Wq|Wk|Wv, 576
    float* ps = buf + PS_OFF;        // [3][32][2]
    float* po = buf + PO_OFF;        // [3][32][2][8]

    int tid = threadIdx.x;
    int bb  = blockIdx.x >> 2;
    int r0  = (blockIdx.x & 3) * NROWS;

    if (tid < 192) {
        ws[tid]       = Wq[tid];
        ws[192 + tid] = Wk[tid];
        ws[384 + tid] = Wv[tid];
    }
    __syncthreads();

    // ---------------- projections: k/v for all 128 tokens -------------------
    {
        int tk = tid >> 1;              // token 0..127
        int cs = (tid & 1) * 12;        // 12 of 24 output cols
        float s[8];
#pragma unroll
        for (int d = 0; d < 8; d++) s[d] = state[(bb * TTK + tk) * 8 + d];
#pragma unroll
        for (int cc = 0; cc < 12; cc++) {
            int c = cs + cc, h = c >> 3, dc = c & 7;
            float ak = 0.f, av = 0.f;
#pragma unroll
            for (int d = 0; d < 8; d++) {
                ak = fmaf(s[d], ws[192 + d * 24 + c], ak);
                av = fmaf(s[d], ws[384 + d * 24 + c], av);
            }
            int off = (h * 128 + tk) * 8 + dc;
            sk[off] = ak; sv[off] = av;
        }
    }
    __syncthreads();

    // ---------------- attention: 192 thr = 3 heads x 32 queries x 2 j-halves
    // softmax shift-invariant -> no max pass; diagonal via predicated zero.
    int h  = tid >> 6;          // 0..3 (3 idle)
    int il = (tid >> 1) & 31;   // local query
    int g  = tid & 1;           // j-half
    float myv[8];
    if (h < 3) {
        int gi = r0 + il;
        float s[8];
#pragma unroll
        for (int d = 0; d < 8; d++) s[d] = state[(bb * TTK + gi) * 8 + d];
        if (h == 0 && g == 0) {
#pragma unroll
            for (int d = 0; d < 8; d++) xst[(24 + d) * XP + il] = s[d];
        }
        // q from registers (64 fma) -- no sq array needed
        float q[8];
        const float* wqs = ws + h * 8;
#pragma unroll
        for (int c = 0; c < 8; c++) {
            float aq = 0.f;
#pragma unroll
            for (int d = 0; d < 8; d++) aq = fmaf(s[d], wqs[d * 24 + c], aq);
            q[c] = aq;
        }
        ulonglong2 q01 = {pack2(q[0], q[1]), pack2(q[2], q[3])};
        ulonglong2 q23 = {pack2(q[4], q[5]), pack2(q[6], q[7])};
        ull o0 = 0, o1 = 0, o2 = 0, o3 = 0;
        float ssum = 0.f;
        const float* skh = sk + h * 1024;
        const float* svh = sv + h * 1024;
        const float scale = 0.3535533905932738f;  // 1/sqrt(8)
        int j0 = g * 64;
#pragma unroll 2
        for (int jj = 0; jj < 64; jj++) {
            int j = j0 + jj;
            const float* kb = skh + j * 8;
            ulonglong2 k01 = *(const ulonglong2*)kb;
            ulonglong2 k23 = *(const ulonglong2*)(kb + 4);
            ull d2 = mul2(q01.x, k01.x);
            d2 = ffma2(q01.y, k01.y, d2);
            d2 = ffma2(q23.x, k23.x, d2);
            d2 = ffma2(q23.y, k23.y, d2);
            float lo, hi; unpack2(d2, lo, hi);
            float p = (j == gi) ? 0.f : __expf((lo + hi) * scale);
            ssum += p;
            ull pp = pack2(p, p);
            const float* vb = svh + j * 8;
            ulonglong2 v01 = *(const ulonglong2*)vb;
            ulonglong2 v23 = *(const ulonglong2*)(vb + 4);
            o0 = ffma2(pp, v01.x, o0);
            o1 = ffma2(pp, v01.y, o1);
            o2 = ffma2(pp, v23.x, o2);
            o3 = ffma2(pp, v23.y, o3);
        }
        int pb = (h * 32 + il) * 2 + g;
        ps[pb] = ssum;
        float ov[8];
        unpack2(o0, ov[0], ov[1]); unpack2(o1, ov[2], ov[3]);
        unpack2(o2, ov[4], ov[5]); unpack2(o3, ov[6], ov[7]);
#pragma unroll
        for (int d = 0; d < 8; d++) po[pb * 8 + d] = ov[d];
#pragma unroll
        for (int d = 0; d < 8; d++) myv[d] = svh[gi * 8 + d];
    }
    __syncthreads();

    if (h < 3 && g == 0) {
        int pb = (h * 32 + il) * 2;
        float inv = 1.0f / (ps[pb] + ps[pb + 1]);
#pragma unroll
        for (int d = 0; d < 8; d++) {
            float o = po[pb * 8 + d] + po[(pb + 1) * 8 + d];
            xst[(h * 8 + d) * XP + il] = o * inv - myv[d];
        }
    }
    __syncthreads();

    // ---------------- phase 1: h1^T = relu(x32 @ W1 + b1) -------------------
    // thread = col n; 32 rows = 16 pairs, k-outer, FFMA2 on broadcast LDS.128
    {
        int n = tid;
        float b1n = b1[n];
        ull acc[16];
        ull B = pack2(b1n, b1n);
#pragma unroll
        for (int p = 0; p < 16; p++) acc[p] = B;
#pragma unroll 4
        for (int k = 0; k < 32; k++) {
            float w = W1[k * 256 + n];
            ull wd = pack2(w, w);
            const float* xr = xst + k * XP;
#pragma unroll
            for (int p = 0; p < 8; p++) {
                ulonglong2 x = *(const ulonglong2*)(xr + 4 * p);
                acc[2 * p]     = ffma2(x.x, wd, acc[2 * p]);
                acc[2 * p + 1] = ffma2(x.y, wd, acc[2 * p + 1]);
            }
        }
        __syncthreads();   // attn views no longer needed; reuse as hs_t
        float* dst = buf + n * HP;   // hs_t[n][0..31]
#pragma unroll
        for (int p = 0; p < 8; p++) {
            float a0, a1v, a2, a3;
            unpack2(acc[2 * p], a0, a1v);
            unpack2(acc[2 * p + 1], a2, a3);
            ulonglong2 st;
            st.x = pack2(fmaxf(a0, 0.f), fmaxf(a1v, 0.f));
            st.y = pack2(fmaxf(a2, 0.f), fmaxf(a3, 0.f));
            *(ulonglong2*)(dst + 4 * p) = st;
        }
    }
    __syncthreads();

    // ---------------- phase 2: h2 = relu(h1 @ W2 + b2) ----------------------
    // 8 warps = 2 rowgroups (16 rows) x 4 colgroups (64 cols)
    // thread: 8 row-pairs x 2 cols = 16 packed accs (32 regs); LDS.128 bcast
    {
        int wid = tid >> 5, lane = tid & 31;
        int rbase = (wid >> 2) * 16;
        int c0 = (wid & 3) * 64 + lane * 2;
        ull a0[8], a1[8];
        {
            float bc0 = b2[c0], bc1 = b2[c0 + 1];
            ull B0 = pack2(bc0, bc0), B1 = pack2(bc1, bc1);
#pragma unroll
            for (int p = 0; p < 8; p++) { a0[p] = B0; a1[p] = B1; }
        }
#pragma unroll 2
        for (int k = 0; k < 256; k++) {
            float2 w = *(const float2*)(W2 + k * 256 + c0);
            ull Wa = pack2(w.x, w.x);
            ull Wb = pack2(w.y, w.y);
            const float* hrow = buf + k * HP + rbase;
#pragma unroll
            for (int jj = 0; jj < 4; jj++) {
                ulonglong2 hx = *(const ulonglong2*)(hrow + 4 * jj);
                a0[2 * jj]     = ffma2(hx.x, Wa, a0[2 * jj]);
                a1[2 * jj]     = ffma2(hx.x, Wb, a1[2 * jj]);
                a0[2 * jj + 1] = ffma2(hx.y, Wa, a0[2 * jj + 1]);
                a1[2 * jj + 1] = ffma2(hx.y, Wb, a1[2 * jj + 1]);
            }
        }
        __syncthreads();   // all hs_t reads done before overwrite
        float* hs2 = buf;  // [32][H2P]
#pragma unroll
        for (int p = 0; p < 8; p++) {
            float l0, h0, l1, h1;
            unpack2(a0[p], l0, h0);
            unpack2(a1[p], l1, h1);
            int r = rbase + 2 * p;
            float2 s0 = {fmaxf(l0, 0.f), fmaxf(l1, 0.f)};
            float2 s1 = {fmaxf(h0, 0.f), fmaxf(h1, 0.f)};
            *(float2*)(hs2 + r * H2P + c0)       = s0;
            *(float2*)(hs2 + (r + 1) * H2P + c0) = s1;
        }
    }
    __syncthreads();

    // ---------------- phase 3: heads + rsample + log_prob -------------------
    // 8 threads/row, 32 k each (float4 loads), shfl-reduce in 8-lane groups.
    {
        int row = tid >> 3, sub = tid & 7;
        const float* hrow = buf + row * H2P + sub * 32;
        const float* wm = Wmu + sub * 64;
        const float* wl = Wls + sub * 64;
        float m0 = 0.f, m1 = 0.f, l0 = 0.f, l1 = 0.f;
#pragma unroll
        for (int k4 = 0; k4 < 8; k4++) {
            float4 hv = *(const float4*)(hrow + 4 * k4);
            float hvv[4] = {hv.x, hv.y, hv.z, hv.w};
#pragma unroll
            for (int e = 0; e < 4; e++) {
                int k = 4 * k4 + e;
                float2 a = *(const float2*)(wm + 2 * k);
                float2 c = *(const float2*)(wl + 2 * k);
                m0 = fmaf(hvv[e], a.x, m0);
                m1 = fmaf(hvv[e], a.y, m1);
                l0 = fmaf(hvv[e], c.x, l0);
                l1 = fmaf(hvv[e], c.y, l1);
            }
        }
#pragma unroll
        for (int d = 4; d > 0; d >>= 1) {
            m0 += __shfl_down_sync(0xFFFFFFFFu, m0, d);
            m1 += __shfl_down_sync(0xFFFFFFFFu, m1, d);
            l0 += __shfl_down_sync(0xFFFFFFFFu, l0, d);
            l1 += __shfl_down_sync(0xFFFFFFFFu, l1, d);
        }
        if (sub == 0) {
            m0 += bmu[0]; m1 += bmu[1]; l0 += bls[0]; l1 += bls[1];
            int grow = bb * TTK + r0 + row;
            float mu[2]  = {tanh_acc(m0), tanh_acc(m1)};
            float lsr[2] = {l0, l1};
            float lp = 0.0f;
#pragma unroll
            for (int o2 = 0; o2 < 2; o2++) {
                // log_std = -20 + 0.5*(2-(-20))*(tanh+1) = -20 + 11*(tanh+1)
                float ls = -20.0f + 11.0f * (tanh_acc(lsr[o2]) + 1.0f);
                float sd = __expf(ls);
                float nz = noise[grow * 2 + o2];
                float z  = mu[o2] + sd * nz;
                float a  = tanh_acc(z);
                out_action[grow * 2 + o2] = a;
                lp += (-0.5f * nz * nz - ls - 0.9189385332046727f)
                      - __logf(1.0f - a * a + 1e-7f);
            }
            out_logp[grow] = lp;
        }
    }
}

// ---------------------------------------------------------------------------
extern "C" void kernel_launch(void* const* d_in, const int* in_sizes, int n_in,
                              void* d_out, int out_size) {
    const float* state = (const float*)d_in[0];
    const float* noise = (const float*)d_in[1];
    const float* Wq  = (const float*)d_in[2];
    const float* Wk  = (const float*)d_in[3];
    const float* Wv  = (const float*)d_in[4];
    const float* W1  = (const float*)d_in[5];
    const float* b1  = (const float*)d_in[6];
    const float* W2  = (const float*)d_in[7];
    const float* b2  = (const float*)d_in[8];
    const float* Wmu = (const float*)d_in[9];
    const float* bmu = (const float*)d_in[10];
    const float* Wls = (const float*)d_in[11];
    const float* bls = (const float*)d_in[12];
    float* out = (float*)d_out;

    cudaFuncSetAttribute(actor_kernel,
                         cudaFuncAttributeMaxDynamicSharedMemorySize, SMEM_BYTES);
    actor_kernel<<<512, 256, SMEM_BYTES>>>(
        state, noise, Wq, Wk, Wv, W1, b1, W2, b2, Wmu, bmu, Wls, bls,
        out /*action*/, out + 32768 /*log_prob*/);
}

// round 13
// speedup vs baseline: 1.3480x; 1.3480x over previous
#include <cuda_runtime.h>
#include <math.h>

// Problem: B=128, T=128, K=8, H=3, HID=256, OUT=2
// grid = 256: bb = blk>>1 (batch), r0 = (blk&1)*64 (row window)
// block = 256 threads, 2 CTAs/SM
#define TTK 128
#define XP  68     // xst pad  (68*4 % 16 == 0 -> LDS.128 legal)
#define HP  68     // hs_t pad
#define H2P 260    // hs2 pad  (multiple of 4 -> float4 rows)
#define XST_FLOATS (32 * XP)            // 2176
#define BUF_FLOATS (256 * HP)           // 17408
#define SMEM_FLOATS (XST_FLOATS + BUF_FLOATS)
#define SMEM_BYTES  (SMEM_FLOATS * 4)   // 78336

typedef unsigned long long ull;

__device__ __forceinline__ ull pack2(float lo, float hi) {
    ull r; asm("mov.b64 %0,{%1,%2};" : "=l"(r) : "f"(lo), "f"(hi)); return r;
}
__device__ __forceinline__ void unpack2(ull v, float& lo, float& hi) {
    asm("mov.b64 {%0,%1},%2;" : "=f"(lo), "=f"(hi) : "l"(v));
}
__device__ __forceinline__ ull ffma2(ull a, ull b, ull c) {
    ull d; asm("fma.rn.f32x2 %0,%1,%2,%3;" : "=l"(d) : "l"(a), "l"(b), "l"(c));
    return d;
}
__device__ __forceinline__ ull mul2(ull a, ull b) {
    ull d; asm("mul.rn.f32x2 %0,%1,%2;" : "=l"(d) : "l"(a), "l"(b)); return d;
}

// Accurate fp32 tanh (fast-math tanhf -> tanh.approx.f32, ~1e-4 ABS error;
// outputs are ~1e-3 scale -> need controlled error).
__device__ __forceinline__ float tanh_acc(float x) {
    float ax = fabsf(x);
    if (ax < 0.25f) {
        float x2 = x * x;
        float p = fmaf(x2, -0.05396825396825397f, 0.13333333333333333f);
        p = fmaf(x2, p, -0.3333333333333333f);
        p = fmaf(x2, p, 1.0f);
        return x * p;
    }
    float t = __expf(2.0f * fminf(ax, 44.0f));
    float r = (t - 1.0f) / (t + 1.0f);
    return copysignf(r, x);
}

__global__ __launch_bounds__(256, 2) void actor_kernel(
    const float* __restrict__ state, const float* __restrict__ noise,
    const float* __restrict__ Wq, const float* __restrict__ Wk,
    const float* __restrict__ Wv,
    const float* __restrict__ W1, const float* __restrict__ b1,
    const float* __restrict__ W2, const float* __restrict__ b2,
    const float* __restrict__ Wmu, const float* __restrict__ bmu,
    const float* __restrict__ Wls, const float* __restrict__ bls,
    float* __restrict__ out_action, float* __restrict__ out_logp) {
    extern __shared__ float sm[];
    float* xst = sm;                 // [32][XP]  x-features transposed
    float* buf = sm + XST_FLOATS;    // union: attn views | hs_t [256][HP] | hs2 [64][H2P]
    float* sq = buf;                 // [3][128][8]
    float* sk = buf + 3072;          // [3][128][8]
    float* sv = buf + 6144;          // [3][128][8]
    float* ws = buf + 9216;          // Wq|Wk|Wv, 576

    int tid  = threadIdx.x;
    int bb   = blockIdx.x >> 1;
    int r0   = (blockIdx.x & 1) * 64;   // local row window [r0, r0+64)

    // ---------------- projections: all 128 tokens' q/k/v ----------------
    if (tid < 192) {
        ws[tid]       = Wq[tid];
        ws[192 + tid] = Wk[tid];
        ws[384 + tid] = Wv[tid];
    }
    __syncthreads();
    {
        int tk = tid >> 1;              // token 0..127
        int cs = (tid & 1) * 12;        // 12 of 24 output cols
        float s[8];
#pragma unroll
        for (int d = 0; d < 8; d++) s[d] = state[(bb * TTK + tk) * 8 + d];
#pragma unroll
        for (int cc = 0; cc < 12; cc++) {
            int c = cs + cc, h = c >> 3, dc = c & 7;
            float aq = 0.f, ak = 0.f, av = 0.f;
#pragma unroll
            for (int d = 0; d < 8; d++) {
                aq = fmaf(s[d], ws[d * 24 + c], aq);
                ak = fmaf(s[d], ws[192 + d * 24 + c], ak);
                av = fmaf(s[d], ws[384 + d * 24 + c], av);
            }
            int off = (h * 128 + tk) * 8 + dc;
            sq[off] = aq; sk[off] = ak; sv[off] = av;
        }
        if ((tid & 1) == 0) {
            int il = tk - r0;
            if ((unsigned)il < 64u) {
#pragma unroll
                for (int d = 0; d < 8; d++) xst[(24 + d) * XP + il] = s[d];
            }
        }
    }
    __syncthreads();

    // ---------------- attention: 192 threads = 3 heads x 64 local queries ---
    // softmax is shift-invariant -> no max pass (scores are O(0.1) here);
    // diagonal excluded by predicated zero (no divergent branch).
    if (tid < 192) {
        int h = tid >> 6, il = tid & 63, gi = r0 + il;
        const float* qb = sq + (h * 128 + gi) * 8;
        ulonglong2 q01 = *(const ulonglong2*)qb;
        ulonglong2 q23 = *(const ulonglong2*)(qb + 4);
        ull o0 = 0, o1 = 0, o2 = 0, o3 = 0;   // 0 bits == packed {0.f,0.f}
        float ssum = 0.f;
        const float* skh = sk + h * 1024;
        const float* svh = sv + h * 1024;
        const float scale = 0.3535533905932738f;  // 1/sqrt(8)
#pragma unroll 2
        for (int j = 0; j < TTK; j++) {
            const float* kb = skh + j * 8;
            ulonglong2 k01 = *(const ulonglong2*)kb;
            ulonglong2 k23 = *(const ulonglong2*)(kb + 4);
            ull d2 = mul2(q01.x, k01.x);
            d2 = ffma2(q01.y, k01.y, d2);
            d2 = ffma2(q23.x, k23.x, d2);
            d2 = ffma2(q23.y, k23.y, d2);
            float lo, hi; unpack2(d2, lo, hi);
            float p = (j == gi) ? 0.f : __expf((lo + hi) * scale);
            ssum += p;
            ull pp = pack2(p, p);
            const float* vb = svh + j * 8;
            ulonglong2 v01 = *(const ulonglong2*)vb;
            ulonglong2 v23 = *(const ulonglong2*)(vb + 4);
            o0 = ffma2(pp, v01.x, o0);
            o1 = ffma2(pp, v01.y, o1);
            o2 = ffma2(pp, v23.x, o2);
            o3 = ffma2(pp, v23.y, o3);
        }
        float inv = 1.0f / ssum;
        const float* myv = svh + gi * 8;
        float ov[8];
        unpack2(o0, ov[0], ov[1]); unpack2(o1, ov[2], ov[3]);
        unpack2(o2, ov[4], ov[5]); unpack2(o3, ov[6], ov[7]);
#pragma unroll
        for (int d = 0; d < 8; d++)
            xst[(h * 8 + d) * XP + il] = ov[d] * inv - myv[d];
    }
    __syncthreads();

    // ---------------- phase 1: h1^T = relu(x32 @ W1 + b1) -------------------
    // thread = col n; 64 local rows = 32 pairs, k-outer, FFMA2.
    {
        int n = tid;
        float b1n = b1[n];
        ull acc[32];
        ull B = pack2(b1n, b1n);
#pragma unroll
        for (int p = 0; p < 32; p++) acc[p] = B;
#pragma unroll 4
        for (int k = 0; k < 32; k++) {
            float w = W1[k * 256 + n];
            ull wd = pack2(w, w);
            const float* xr = xst + k * XP;
#pragma unroll
            for (int p = 0; p < 16; p++) {
                ulonglong2 x = *(const ulonglong2*)(xr + 4 * p);
                acc[2 * p]     = ffma2(x.x, wd, acc[2 * p]);
                acc[2 * p + 1] = ffma2(x.y, wd, acc[2 * p + 1]);
            }
        }
        float* dst = buf + n * HP;    // hs_t[n][0..63]  (overwrites attn views)
#pragma unroll
        for (int p = 0; p < 16; p++) {
            float a0, a1v, a2, a3;
            unpack2(acc[2 * p], a0, a1v);
            unpack2(acc[2 * p + 1], a2, a3);
            ulonglong2 st;
            st.x = pack2(fmaxf(a0, 0.f), fmaxf(a1v, 0.f));
            st.y = pack2(fmaxf(a2, 0.f), fmaxf(a3, 0.f));
            *(ulonglong2*)(dst + 4 * p) = st;
        }
    }
    __syncthreads();

    // ---------------- phase 2: h2 = relu(h1 @ W2 + b2) ----------------------
    // 8 warps = 4 rowgroups (16 rows) x 2 colgroups (128 cols)
    // thread: 8 row-pairs x 4 cols; per k: 1 LDG.128 + 4 bcast LDS.128 + 32
    // FFMA2 (ratio 8:1 -> LDS crossbar hidden under fma issue).
    {
        int wid = tid >> 5, lane = tid & 31;
        int rbase = (wid >> 1) * 16;
        int c0 = (wid & 1) * 128 + lane * 4;
        ull acc[4][8];
        {
            float4 bc = *(const float4*)(b2 + c0);
            float bcv[4] = {bc.x, bc.y, bc.z, bc.w};
#pragma unroll
            for (int c = 0; c < 4; c++) {
                ull B = pack2(bcv[c], bcv[c]);
#pragma unroll
                for (int p = 0; p < 8; p++) acc[c][p] = B;
            }
        }
#pragma unroll 2
        for (int k = 0; k < 256; k++) {
            float4 w = *(const float4*)(W2 + k * 256 + c0);
            ull W0 = pack2(w.x, w.x);
            ull W1d = pack2(w.y, w.y);
            ull W2d = pack2(w.z, w.z);
            ull W3 = pack2(w.w, w.w);
            const float* hrow = buf + k * HP + rbase;
            ulonglong2 hA = *(const ulonglong2*)(hrow);
            ulonglong2 hB = *(const ulonglong2*)(hrow + 4);
            ulonglong2 hC = *(const ulonglong2*)(hrow + 8);
            ulonglong2 hD = *(const ulonglong2*)(hrow + 12);
            ull hx[8] = {hA.x, hA.y, hB.x, hB.y, hC.x, hC.y, hD.x, hD.y};
#pragma unroll
            for (int p = 0; p < 8; p++) {
                acc[0][p] = ffma2(hx[p], W0, acc[0][p]);
                acc[1][p] = ffma2(hx[p], W1d, acc[1][p]);
                acc[2][p] = ffma2(hx[p], W2d, acc[2][p]);
                acc[3][p] = ffma2(hx[p], W3, acc[3][p]);
            }
        }
        __syncthreads();   // all hs_t reads done before overwrite
        float* hs2 = buf;  // [64][H2P]
#pragma unroll
        for (int p = 0; p < 8; p++) {
            float lo[4], hi[4];
#pragma unroll
            for (int c = 0; c < 4; c++) unpack2(acc[c][p], lo[c], hi[c]);
            int r = rbase + 2 * p;
            float4 s0 = {fmaxf(lo[0], 0.f), fmaxf(lo[1], 0.f),
                         fmaxf(lo[2], 0.f), fmaxf(lo[3], 0.f)};
            float4 s1 = {fmaxf(hi[0], 0.f), fmaxf(hi[1], 0.f),
                         fmaxf(hi[2], 0.f), fmaxf(hi[3], 0.f)};
            *(float4*)(hs2 + r * H2P + c0)       = s0;
            *(float4*)(hs2 + (r + 1) * H2P + c0) = s1;
        }
    }
    __syncthreads();

    // ---------------- phase 3: heads + rsample + log_prob -------------------
    // 4 threads/row, 64 k each, shfl-reduce in 4-lane groups.
    {
        int row = tid >> 2, sub = tid & 3;
        const float* hrow = buf + row * H2P + sub * 64;
        const float* wm = Wmu + sub * 128;
        const float* wl = Wls + sub * 128;
        float m0 = 0.f, m1 = 0.f, l0 = 0.f, l1 = 0.f;
#pragma unroll 8
        for (int k = 0; k < 64; k++) {
            float hv = hrow[k];
            float2 a = *(const float2*)(wm + 2 * k);
            float2 c = *(const float2*)(wl + 2 * k);
            m0 = fmaf(hv, a.x, m0);
            m1 = fmaf(hv, a.y, m1);
            l0 = fmaf(hv, c.x, l0);
            l1 = fmaf(hv, c.y, l1);
        }
#pragma unroll
        for (int d = 2; d > 0; d >>= 1) {
            m0 += __shfl_down_sync(0xFFFFFFFFu, m0, d);
            m1 += __shfl_down_sync(0xFFFFFFFFu, m1, d);
            l0 += __shfl_down_sync(0xFFFFFFFFu, l0, d);
            l1 += __shfl_down_sync(0xFFFFFFFFu, l1, d);
        }
        if (sub == 0) {
            m0 += bmu[0]; m1 += bmu[1]; l0 += bls[0]; l1 += bls[1];
            int grow = bb * TTK + r0 + row;
            float mu[2]  = {tanh_acc(m0), tanh_acc(m1)};
            float lsr[2] = {l0, l1};
            float lp = 0.0f;
#pragma unroll
            for (int o2 = 0; o2 < 2; o2++) {
                // log_std = -20 + 0.5*(2-(-20))*(tanh+1) = -20 + 11*(tanh+1)
                float ls = -20.0f + 11.0f * (tanh_acc(lsr[o2]) + 1.0f);
                float sd = __expf(ls);
                float nz = noise[grow * 2 + o2];
                float z  = mu[o2] + sd * nz;
                float a  = tanh_acc(z);
                out_action[grow * 2 + o2] = a;
                lp += (-0.5f * nz * nz - ls - 0.9189385332046727f)
                      - __logf(1.0f - a * a + 1e-7f);
            }
            out_logp[grow] = lp;
        }
    }
}

// ---------------------------------------------------------------------------
extern "C" void kernel_launch(void* const* d_in, const int* in_sizes, int n_in,
                              void* d_out, int out_size) {
    const float* state = (const float*)d_in[0];
    const float* noise = (const float*)d_in[1];
    const float* Wq  = (const float*)d_in[2];
    const float* Wk  = (const float*)d_in[3];
    const float* Wv  = (const float*)d_in[4];
    const float* W1  = (const float*)d_in[5];
    const float* b1  = (const float*)d_in[6];
    const float* W2  = (const float*)d_in[7];
    const float* b2  = (const float*)d_in[8];
    const float* Wmu = (const float*)d_in[9];
    const float* bmu = (const float*)d_in[10];
    const float* Wls = (const float*)d_in[11];
    const float* bls = (const float*)d_in[12];
    float* out = (float*)d_out;

    cudaFuncSetAttribute(actor_kernel,
                         cudaFuncAttributeMaxDynamicSharedMemorySize, SMEM_BYTES);
    actor_kernel<<<256, 256, SMEM_BYTES>>>(
        state, noise, Wq, Wk, Wv, W1, b1, W2, b2, Wmu, bmu, Wls, bls,
        out /*action*/, out + 32768 /*log_prob*/);
}

// round 14
// speedup vs baseline: 1.4133x; 1.0485x over previous
#include <cuda_runtime.h>
#include <cuda_bf16.h>
#include <math.h>

// Problem: B=128, T=128, K=8, H=3, HID=256, OUT=2
// grid 256: bb = blk>>1, r0 = (blk&1)*64. block 256, 2 CTAs/SM.
#define TTK 128
#define XP  68       // xst pad
#define HB  264      // h1 bf16 row pitch (conflict-free A-frag loads)
#define WB  20       // Wt bf16 row pitch (conflict-free B-frag loads)
#define H2P 260      // hs2 fp32 row pitch
#define XST_FLOATS (32 * XP)                 // 2176
#define BUF_FLOATS 22016                     // max union occupancy (h1hi/lo + Wt)
#define SMEM_FLOATS (XST_FLOATS + BUF_FLOATS)
#define SMEM_BYTES  (SMEM_FLOATS * 4)        // 96768

typedef unsigned long long ull;

__device__ __forceinline__ ull pack2(float lo, float hi) {
    ull r; asm("mov.b64 %0,{%1,%2};" : "=l"(r) : "f"(lo), "f"(hi)); return r;
}
__device__ __forceinline__ void unpack2(ull v, float& lo, float& hi) {
    asm("mov.b64 {%0,%1},%2;" : "=f"(lo), "=f"(hi) : "l"(v));
}
__device__ __forceinline__ ull ffma2(ull a, ull b, ull c) {
    ull d; asm("fma.rn.f32x2 %0,%1,%2,%3;" : "=l"(d) : "l"(a), "l"(b), "l"(c));
    return d;
}
__device__ __forceinline__ ull mul2(ull a, ull b) {
    ull d; asm("mul.rn.f32x2 %0,%1,%2;" : "=l"(d) : "l"(a), "l"(b)); return d;
}
__device__ __forceinline__ void mma_bf16(float* c, const unsigned* a,
                                         const unsigned* b) {
    asm volatile(
        "mma.sync.aligned.m16n8k16.row.col.f32.bf16.bf16.f32 "
        "{%0,%1,%2,%3}, {%4,%5,%6,%7}, {%8,%9}, {%0,%1,%2,%3};"
        : "+f"(c[0]), "+f"(c[1]), "+f"(c[2]), "+f"(c[3])
        : "r"(a[0]), "r"(a[1]), "r"(a[2]), "r"(a[3]), "r"(b[0]), "r"(b[1]));
}

// Accurate fp32 tanh (fast-math tanhf -> tanh.approx.f32, ~1e-4 ABS error;
// outputs are ~1e-3 scale -> need controlled error).
__device__ __forceinline__ float tanh_acc(float x) {
    float ax = fabsf(x);
    if (ax < 0.25f) {
        float x2 = x * x;
        float p = fmaf(x2, -0.05396825396825397f, 0.13333333333333333f);
        p = fmaf(x2, p, -0.3333333333333333f);
        p = fmaf(x2, p, 1.0f);
        return x * p;
    }
    float t = __expf(2.0f * fminf(ax, 44.0f));
    float r = (t - 1.0f) / (t + 1.0f);
    return copysignf(r, x);
}

__global__ __launch_bounds__(256, 2) void actor_kernel(
    const float* __restrict__ state, const float* __restrict__ noise,
    const float* __restrict__ Wq, const float* __restrict__ Wk,
    const float* __restrict__ Wv,
    const float* __restrict__ W1, const float* __restrict__ b1,
    const float* __restrict__ W2, const float* __restrict__ b2,
    const float* __restrict__ Wmu, const float* __restrict__ bmu,
    const float* __restrict__ Wls, const float* __restrict__ bls,
    float* __restrict__ out_action, float* __restrict__ out_logp) {
    extern __shared__ float sm[];
    float* xst = sm;                 // [32][XP] x-features transposed
    float* buf = sm + XST_FLOATS;    // union region
    // attention views
    float* sq = buf;                 // [3][128][8]
    float* sk = buf + 3072;
    float* sv = buf + 6144;
    float* ws = buf + 9216;          // 576
    // phase 1/2 views (bf16)
    __nv_bfloat16* h1hi = (__nv_bfloat16*)buf;            // [64][HB]
    __nv_bfloat16* h1lo = h1hi + 64 * HB;                 // [64][HB]
    __nv_bfloat16* wt_hi = h1lo + 64 * HB;                // [256][WB]
    __nv_bfloat16* wt_lo = wt_hi + 256 * WB;              // [256][WB]

    int tid  = threadIdx.x;
    int bb   = blockIdx.x >> 1;
    int r0   = (blockIdx.x & 1) * 64;   // local row window [r0, r0+64)

    // ---------------- projections: all 128 tokens' q/k/v ----------------
    if (tid < 192) {
        ws[tid]       = Wq[tid];
        ws[192 + tid] = Wk[tid];
        ws[384 + tid] = Wv[tid];
    }
    __syncthreads();
    {
        int tk = tid >> 1;              // token 0..127
        int cs = (tid & 1) * 12;        // 12 of 24 output cols
        float s[8];
#pragma unroll
        for (int d = 0; d < 8; d++) s[d] = state[(bb * TTK + tk) * 8 + d];
#pragma unroll
        for (int cc = 0; cc < 12; cc++) {
            int c = cs + cc, h = c >> 3, dc = c & 7;
            float aq = 0.f, ak = 0.f, av = 0.f;
#pragma unroll
            for (int d = 0; d < 8; d++) {
                aq = fmaf(s[d], ws[d * 24 + c], aq);
                ak = fmaf(s[d], ws[192 + d * 24 + c], ak);
                av = fmaf(s[d], ws[384 + d * 24 + c], av);
            }
            int off = (h * 128 + tk) * 8 + dc;
            sq[off] = aq; sk[off] = ak; sv[off] = av;
        }
        if ((tid & 1) == 0) {
            int il = tk - r0;
            if ((unsigned)il < 64u) {
#pragma unroll
                for (int d = 0; d < 8; d++) xst[(24 + d) * XP + il] = s[d];
            }
        }
    }
    __syncthreads();

    // ---------------- attention: 192 threads = 3 heads x 64 local queries ---
    // softmax shift-invariant -> no max pass; diagonal via predicated zero.
    if (tid < 192) {
        int h = tid >> 6, il = tid & 63, gi = r0 + il;
        const float* qb = sq + (h * 128 + gi) * 8;
        ulonglong2 q01 = *(const ulonglong2*)qb;
        ulonglong2 q23 = *(const ulonglong2*)(qb + 4);
        ull o0 = 0, o1 = 0, o2 = 0, o3 = 0;
        float ssum = 0.f;
        const float* skh = sk + h * 1024;
        const float* svh = sv + h * 1024;
        const float scale = 0.3535533905932738f;  // 1/sqrt(8)
#pragma unroll 2
        for (int j = 0; j < TTK; j++) {
            const float* kb = skh + j * 8;
            ulonglong2 k01 = *(const ulonglong2*)kb;
            ulonglong2 k23 = *(const ulonglong2*)(kb + 4);
            ull d2 = mul2(q01.x, k01.x);
            d2 = ffma2(q01.y, k01.y, d2);
            d2 = ffma2(q23.x, k23.x, d2);
            d2 = ffma2(q23.y, k23.y, d2);
            float lo, hi; unpack2(d2, lo, hi);
            float p = (j == gi) ? 0.f : __expf((lo + hi) * scale);
            ssum += p;
            ull pp = pack2(p, p);
            const float* vb = svh + j * 8;
            ulonglong2 v01 = *(const ulonglong2*)vb;
            ulonglong2 v23 = *(const ulonglong2*)(vb + 4);
            o0 = ffma2(pp, v01.x, o0);
            o1 = ffma2(pp, v01.y, o1);
            o2 = ffma2(pp, v23.x, o2);
            o3 = ffma2(pp, v23.y, o3);
        }
        float inv = 1.0f / ssum;
        const float* myv = svh + gi * 8;
        float ov[8];
        unpack2(o0, ov[0], ov[1]); unpack2(o1, ov[2], ov[3]);
        unpack2(o2, ov[4], ov[5]); unpack2(o3, ov[6], ov[7]);
#pragma unroll
        for (int d = 0; d < 8; d++)
            xst[(h * 8 + d) * XP + il] = ov[d] * inv - myv[d];
    }
    __syncthreads();

    // ---------------- phase 1: h1 = relu(x32 @ W1 + b1), emit bf16 hi/lo ----
    // thread = col n; 64 local rows = 32 packed pairs, k-outer, FFMA2.
    {
        int n = tid;
        float b1n = b1[n];
        ull acc[32];
        ull B = pack2(b1n, b1n);
#pragma unroll
        for (int p = 0; p < 32; p++) acc[p] = B;
#pragma unroll 4
        for (int k = 0; k < 32; k++) {
            float w = W1[k * 256 + n];
            ull wd = pack2(w, w);
            const float* xr = xst + k * XP;
#pragma unroll
            for (int p = 0; p < 16; p++) {
                ulonglong2 x = *(const ulonglong2*)(xr + 4 * p);
                acc[2 * p]     = ffma2(x.x, wd, acc[2 * p]);
                acc[2 * p + 1] = ffma2(x.y, wd, acc[2 * p + 1]);
            }
        }
        __syncthreads();   // attn views dead; buf becomes h1hi/h1lo
#pragma unroll
        for (int q = 0; q < 32; q++) {
            float v0, v1;
            unpack2(acc[q], v0, v1);
            v0 = fmaxf(v0, 0.f);
            v1 = fmaxf(v1, 0.f);
            __nv_bfloat16 h0 = __float2bfloat16(v0);
            __nv_bfloat16 h1v = __float2bfloat16(v1);
            h1hi[(2 * q) * HB + n]     = h0;
            h1hi[(2 * q + 1) * HB + n] = h1v;
            h1lo[(2 * q) * HB + n]     = __float2bfloat16(v0 - __bfloat162float(h0));
            h1lo[(2 * q + 1) * HB + n] = __float2bfloat16(v1 - __bfloat162float(h1v));
        }
    }
    __syncthreads();

    // ---------------- phase 2: h2 = relu(h1 @ W2 + b2) via bf16 MMA ---------
    // warp w: rows m0 = (w>>1)*16, cols nbase = (w&1)*128 (16 n-tiles of 8).
    // Split GEMM: Ahi*Bhi + Alo*Bhi + Ahi*Blo, fp32 accumulate.
    {
        int wid = tid >> 5, lane = tid & 31;
        int g = lane >> 2, t = lane & 3;
        int m0 = (wid >> 1) * 16;
        int nbase = (wid & 1) * 128;
        float c[16][4];
#pragma unroll
        for (int nt = 0; nt < 16; nt++)
#pragma unroll
            for (int e = 0; e < 4; e++) c[nt][e] = 0.f;

        for (int kt = 0; kt < 16; kt++) {
            int k0 = kt * 16;
            // stage W2 k-tile transposed as bf16 hi/lo: Wt[n][k_local]
#pragma unroll 4
            for (int r = 0; r < 16; r++) {
                float w = W2[(k0 + r) * 256 + tid];
                __nv_bfloat16 hi = __float2bfloat16(w);
                wt_hi[tid * WB + r] = hi;
                wt_lo[tid * WB + r] = __float2bfloat16(w - __bfloat162float(hi));
            }
            __syncthreads();
            // A fragments (m16k16 row-major): a0={A[g][2t],A[g][2t+1]},
            // a1=rows+8, a2/a3 = k+8 halves.
            unsigned ahi[4], alo[4];
            {
                int ra = m0 + g, rb = ra + 8, kc = k0 + 2 * t;
                ahi[0] = *(const unsigned*)(h1hi + ra * HB + kc);
                ahi[1] = *(const unsigned*)(h1hi + rb * HB + kc);
                ahi[2] = *(const unsigned*)(h1hi + ra * HB + kc + 8);
                ahi[3] = *(const unsigned*)(h1hi + rb * HB + kc + 8);
                alo[0] = *(const unsigned*)(h1lo + ra * HB + kc);
                alo[1] = *(const unsigned*)(h1lo + rb * HB + kc);
                alo[2] = *(const unsigned*)(h1lo + ra * HB + kc + 8);
                alo[3] = *(const unsigned*)(h1lo + rb * HB + kc + 8);
            }
#pragma unroll
            for (int nt = 0; nt < 16; nt++) {
                int n0 = nbase + 8 * nt;
                // B fragments (k16n8 col-major): b0={B[2t][g],B[2t+1][g]},
                // b1 = k+8 half; Wt is n-major so pairs are adjacent.
                const __nv_bfloat16* wrh = wt_hi + (n0 + g) * WB + 2 * t;
                const __nv_bfloat16* wrl = wt_lo + (n0 + g) * WB + 2 * t;
                unsigned bh[2] = {*(const unsigned*)wrh,
                                  *(const unsigned*)(wrh + 8)};
                unsigned bl[2] = {*(const unsigned*)wrl,
                                  *(const unsigned*)(wrl + 8)};
                mma_bf16(c[nt], ahi, bh);
                mma_bf16(c[nt], alo, bh);
                mma_bf16(c[nt], ahi, bl);
            }
            __syncthreads();   // mma reads done before next stage overwrites Wt
        }
        // epilogue: bias + relu -> hs2 fp32 (aliases h1 region; fenced above)
        float* hs2 = buf;  // [64][H2P]
        int ra = m0 + g, rb = ra + 8;
#pragma unroll
        for (int nt = 0; nt < 16; nt++) {
            int col = nbase + 8 * nt + 2 * t;
            float2 bv = *(const float2*)(b2 + col);
            float2 s0 = {fmaxf(c[nt][0] + bv.x, 0.f),
                         fmaxf(c[nt][1] + bv.y, 0.f)};
            float2 s1 = {fmaxf(c[nt][2] + bv.x, 0.f),
                         fmaxf(c[nt][3] + bv.y, 0.f)};
            *(float2*)(hs2 + ra * H2P + col) = s0;
            *(float2*)(hs2 + rb * H2P + col) = s1;
        }
    }
    __syncthreads();

    // ---------------- phase 3: heads + rsample + log_prob -------------------
    // 4 threads/row, 64 k each, shfl-reduce in 4-lane groups.
    {
        int row = tid >> 2, sub = tid & 3;
        const float* hrow = buf + row * H2P + sub * 64;
        const float* wm = Wmu + sub * 128;
        const float* wl = Wls + sub * 128;
        float m0 = 0.f, m1 = 0.f, l0 = 0.f, l1 = 0.f;
#pragma unroll 8
        for (int k = 0; k < 64; k++) {
            float hv = hrow[k];
            float2 a = *(const float2*)(wm + 2 * k);
            float2 c = *(const float2*)(wl + 2 * k);
            m0 = fmaf(hv, a.x, m0);
            m1 = fmaf(hv, a.y, m1);
            l0 = fmaf(hv, c.x, l0);
            l1 = fmaf(hv, c.y, l1);
        }
#pragma unroll
        for (int d = 2; d > 0; d >>= 1) {
            m0 += __shfl_down_sync(0xFFFFFFFFu, m0, d);
            m1 += __shfl_down_sync(0xFFFFFFFFu, m1, d);
            l0 += __shfl_down_sync(0xFFFFFFFFu, l0, d);
            l1 += __shfl_down_sync(0xFFFFFFFFu, l1, d);
        }
        if (sub == 0) {
            m0 += bmu[0]; m1 += bmu[1]; l0 += bls[0]; l1 += bls[1];
            int grow = bb * TTK + r0 + row;
            float mu[2]  = {tanh_acc(m0), tanh_acc(m1)};
            float lsr[2] = {l0, l1};
            float lp = 0.0f;
#pragma unroll
            for (int o2 = 0; o2 < 2; o2++) {
                // log_std = -20 + 0.5*(2-(-20))*(tanh+1) = -20 + 11*(tanh+1)
                float ls = -20.0f + 11.0f * (tanh_acc(lsr[o2]) + 1.0f);
                float sd = __expf(ls);
                float nz = noise[grow * 2 + o2];
                float z  = mu[o2] + sd * nz;
                float a  = tanh_acc(z);
                out_action[grow * 2 + o2] = a;
                lp += (-0.5f * nz * nz - ls - 0.9189385332046727f)
                      - __logf(1.0f - a * a + 1e-7f);
            }
            out_logp[grow] = lp;
        }
    }
}

// ---------------------------------------------------------------------------
extern "C" void kernel_launch(void* const* d_in, const int* in_sizes, int n_in,
                              void* d_out, int out_size) {
    const float* state = (const float*)d_in[0];
    const float* noise = (const float*)d_in[1];
    const float* Wq  = (const float*)d_in[2];
    const float* Wk  = (const float*)d_in[3];
    const float* Wv  = (const float*)d_in[4];
    const float* W1  = (const float*)d_in[5];
    const float* b1  = (const float*)d_in[6];
    const float* W2  = (const float*)d_in[7];
    const float* b2  = (const float*)d_in[8];
    const float* Wmu = (const float*)d_in[9];
    const float* bmu = (const float*)d_in[10];
    const float* Wls = (const float*)d_in[11];
    const float* bls = (const float*)d_in[12];
    float* out = (float*)d_out;

    cudaFuncSetAttribute(actor_kernel,
                         cudaFuncAttributeMaxDynamicSharedMemorySize, SMEM_BYTES);
    actor_kernel<<<256, 256, SMEM_BYTES>>>(
        state, noise, Wq, Wk, Wv, W1, b1, W2, b2, Wmu, bmu, Wls, bls,
        out /*action*/, out + 32768 /*log_prob*/);
}

// round 16
// speedup vs baseline: 1.5842x; 1.1209x over previous
#include <cuda_runtime.h>
#include <cuda_bf16.h>
#include <math.h>

// Problem: B=128, T=128, K=8, H=3, HID=256, OUT=2
// grid 256: bb = blk>>1, r0 = (blk&1)*64. block 256, 2 CTAs/SM.
#define TTK 128
#define XP  68       // xst pad (floats)
#define HB  264      // h1 bf16 row pitch (528 B: LDSM conflict-free)
#define WB  24       // wt bf16 row pitch (48 B: LDSM conflict-free)
#define H2P 260      // hs2 fp32 row pitch
#define XST_FLOATS (32 * XP)                 // 2176
#define H1_ELEMS (64 * HB)                   // 16896 bf16
#define WT_ELEMS (256 * WB)                  // 6144 bf16
#define BUF_FLOATS ((H1_ELEMS * 2 + WT_ELEMS * 2) / 2)   // 23040
#define SMEM_FLOATS (XST_FLOATS + BUF_FLOATS)            // 25216
#define SMEM_BYTES  (SMEM_FLOATS * 4)                    // 100864

typedef unsigned long long ull;

__device__ __forceinline__ ull pack2(float lo, float hi) {
    ull r; asm("mov.b64 %0,{%1,%2};" : "=l"(r) : "f"(lo), "f"(hi)); return r;
}
__device__ __forceinline__ void unpack2(ull v, float& lo, float& hi) {
    asm("mov.b64 {%0,%1},%2;" : "=f"(lo), "=f"(hi) : "l"(v));
}
__device__ __forceinline__ ull ffma2(ull a, ull b, ull c) {
    ull d; asm("fma.rn.f32x2 %0,%1,%2,%3;" : "=l"(d) : "l"(a), "l"(b), "l"(c));
    return d;
}
__device__ __forceinline__ ull mul2(ull a, ull b) {
    ull d; asm("mul.rn.f32x2 %0,%1,%2;" : "=l"(d) : "l"(a), "l"(b)); return d;
}
__device__ __forceinline__ void mma_bf16(float* c, const unsigned* a,
                                         const unsigned* b) {
    asm volatile(
        "mma.sync.aligned.m16n8k16.row.col.f32.bf16.bf16.f32 "
        "{%0,%1,%2,%3}, {%4,%5,%6,%7}, {%8,%9}, {%0,%1,%2,%3};"
        : "+f"(c[0]), "+f"(c[1]), "+f"(c[2]), "+f"(c[3])
        : "r"(a[0]), "r"(a[1]), "r"(a[2]), "r"(a[3]), "r"(b[0]), "r"(b[1]));
}
__device__ __forceinline__ void ldsm_x4(unsigned* r, unsigned addr) {
    asm volatile(
        "ldmatrix.sync.aligned.m8n8.x4.shared.b16 {%0,%1,%2,%3}, [%4];"
        : "=r"(r[0]), "=r"(r[1]), "=r"(r[2]), "=r"(r[3]) : "r"(addr));
}
__device__ __forceinline__ unsigned su32(const void* p) {
    unsigned a;
    asm("{.reg .u64 t; cvta.to.shared.u64 t, %1; cvt.u32.u64 %0, t;}"
        : "=r"(a) : "l"(p));
    return a;
}

// Accurate fp32 tanh (fast-math tanhf -> tanh.approx.f32, ~1e-4 ABS error;
// outputs are ~1e-3 scale -> need controlled error).
__device__ __forceinline__ float tanh_acc(float x) {
    float ax = fabsf(x);
    if (ax < 0.25f) {
        float x2 = x * x;
        float p = fmaf(x2, -0.05396825396825397f, 0.13333333333333333f);
        p = fmaf(x2, p, -0.3333333333333333f);
        p = fmaf(x2, p, 1.0f);
        return x * p;
    }
    float t = __expf(2.0f * fminf(ax, 44.0f));
    float r = (t - 1.0f) / (t + 1.0f);
    return copysignf(r, x);
}

__global__ __launch_bounds__(256, 2) void actor_kernel(
    const float* __restrict__ state, const float* __restrict__ noise,
    const float* __restrict__ Wq, const float* __restrict__ Wk,
    const float* __restrict__ Wv,
    const float* __restrict__ W1, const float* __restrict__ b1,
    const float* __restrict__ W2, const float* __restrict__ b2,
    const float* __restrict__ Wmu, const float* __restrict__ bmu,
    const float* __restrict__ Wls, const float* __restrict__ bls,
    float* __restrict__ out_action, float* __restrict__ out_logp) {
    extern __shared__ float sm[];
    float* xst = sm;                 // [32][XP] x-features transposed
    float* buf = sm + XST_FLOATS;    // union region
    // attention views (first ~39 KB of buf)
    float* sq = buf;                 // [3][128][8]
    float* sk = buf + 3072;
    float* sv = buf + 6144;
    float* ws = buf + 9216;          // 576
    // phase 1/2 views (bf16)
    __nv_bfloat16* h1hi = (__nv_bfloat16*)buf;      // [64][HB]
    __nv_bfloat16* h1lo = h1hi + H1_ELEMS;          // [64][HB]
    __nv_bfloat16* wt_hi = h1lo + H1_ELEMS;         // [256][WB] (beyond attn views)
    __nv_bfloat16* wt_lo = wt_hi + WT_ELEMS;        // [256][WB]

    int tid  = threadIdx.x;
    int bb   = blockIdx.x >> 1;
    int r0   = (blockIdx.x & 1) * 64;   // local row window [r0, r0+64)

    // ---------------- projections: all 128 tokens' q/k/v ----------------
    if (tid < 192) {
        ws[tid]       = Wq[tid];
        ws[192 + tid] = Wk[tid];
        ws[384 + tid] = Wv[tid];
    }
    __syncthreads();
    {
        int tk = tid >> 1;              // token 0..127
        int cs = (tid & 1) * 12;        // 12 of 24 output cols
        float s[8];
#pragma unroll
        for (int d = 0; d < 8; d++) s[d] = state[(bb * TTK + tk) * 8 + d];
#pragma unroll
        for (int cc = 0; cc < 12; cc++) {
            int c = cs + cc, h = c >> 3, dc = c & 7;
            float aq = 0.f, ak = 0.f, av = 0.f;
#pragma unroll
            for (int d = 0; d < 8; d++) {
                aq = fmaf(s[d], ws[d * 24 + c], aq);
                ak = fmaf(s[d], ws[192 + d * 24 + c], ak);
                av = fmaf(s[d], ws[384 + d * 24 + c], av);
            }
            int off = (h * 128 + tk) * 8 + dc;
            sq[off] = aq; sk[off] = ak; sv[off] = av;
        }
        if ((tid & 1) == 0) {
            int il = tk - r0;
            if ((unsigned)il < 64u) {
#pragma unroll
                for (int d = 0; d < 8; d++) xst[(24 + d) * XP + il] = s[d];
            }
        }
    }
    // Prefetch W2 stage 0 (rows 0..15) — consumed in phase 2; latency hides
    // behind attention + phase 1.
    float wreg[16];
#pragma unroll
    for (int r = 0; r < 16; r++) wreg[r] = W2[r * 256 + tid];
    __syncthreads();

    // ---------------- attention: 192 threads = 3 heads x 64 local queries ---
    // softmax shift-invariant -> no max pass; diagonal via predicated zero.
    if (tid < 192) {
        int h = tid >> 6, il = tid & 63, gi = r0 + il;
        const float* qb = sq + (h * 128 + gi) * 8;
        ulonglong2 q01 = *(const ulonglong2*)qb;
        ulonglong2 q23 = *(const ulonglong2*)(qb + 4);
        ull o0 = 0, o1 = 0, o2 = 0, o3 = 0;
        float ssum = 0.f;
        const float* skh = sk + h * 1024;
        const float* svh = sv + h * 1024;
        const float scale = 0.3535533905932738f;  // 1/sqrt(8)
#pragma unroll 2
        for (int j = 0; j < TTK; j++) {
            const float* kb = skh + j * 8;
            ulonglong2 k01 = *(const ulonglong2*)kb;
            ulonglong2 k23 = *(const ulonglong2*)(kb + 4);
            ull d2 = mul2(q01.x, k01.x);
            d2 = ffma2(q01.y, k01.y, d2);
            d2 = ffma2(q23.x, k23.x, d2);
            d2 = ffma2(q23.y, k23.y, d2);
            float lo, hi; unpack2(d2, lo, hi);
            float p = (j == gi) ? 0.f : __expf((lo + hi) * scale);
            ssum += p;
            ull pp = pack2(p, p);
            const float* vb = svh + j * 8;
            ulonglong2 v01 = *(const ulonglong2*)vb;
            ulonglong2 v23 = *(const ulonglong2*)(vb + 4);
            o0 = ffma2(pp, v01.x, o0);
            o1 = ffma2(pp, v01.y, o1);
            o2 = ffma2(pp, v23.x, o2);
            o3 = ffma2(pp, v23.y, o3);
        }
        float inv = 1.0f / ssum;
        const float* myv = svh + gi * 8;
        float ov[8];
        unpack2(o0, ov[0], ov[1]); unpack2(o1, ov[2], ov[3]);
        unpack2(o2, ov[4], ov[5]); unpack2(o3, ov[6], ov[7]);
#pragma unroll
        for (int d = 0; d < 8; d++)
            xst[(h * 8 + d) * XP + il] = ov[d] * inv - myv[d];
    }
    __syncthreads();

    // ---------------- phase 1: h1 = relu(x32 @ W1 + b1), emit bf16 hi/lo ----
    // thread = col n; 64 local rows = 32 packed pairs, k-outer, FFMA2.
    {
        int n = tid;
        float b1n = b1[n];
        ull acc[32];
        ull B = pack2(b1n, b1n);
#pragma unroll
        for (int p = 0; p < 32; p++) acc[p] = B;
#pragma unroll 4
        for (int k = 0; k < 32; k++) {
            float w = W1[k * 256 + n];
            ull wd = pack2(w, w);
            const float* xr = xst + k * XP;
#pragma unroll
            for (int p = 0; p < 16; p++) {
                ulonglong2 x = *(const ulonglong2*)(xr + 4 * p);
                acc[2 * p]     = ffma2(x.x, wd, acc[2 * p]);
                acc[2 * p + 1] = ffma2(x.y, wd, acc[2 * p + 1]);
            }
        }
        __syncthreads();   // attn views dead; buf becomes h1hi/h1lo
#pragma unroll
        for (int q = 0; q < 32; q++) {
            float v0, v1;
            unpack2(acc[q], v0, v1);
            v0 = fmaxf(v0, 0.f);
            v1 = fmaxf(v1, 0.f);
            __nv_bfloat16 h0 = __float2bfloat16(v0);
            __nv_bfloat16 h1v = __float2bfloat16(v1);
            h1hi[(2 * q) * HB + n]     = h0;
            h1hi[(2 * q + 1) * HB + n] = h1v;
            h1lo[(2 * q) * HB + n]     = __float2bfloat16(v0 - __bfloat162float(h0));
            h1lo[(2 * q + 1) * HB + n] = __float2bfloat16(v1 - __bfloat162float(h1v));
        }
    }
    __syncthreads();

    // ---------------- phase 2: h2 = relu(h1 @ W2 + b2) via bf16 MMA + LDSM --
    // warp: rows m0=(w>>1)*16, cols nbase=(w&1)*128 (16 n-tiles of 8).
    // Split GEMM: Ahi*Bhi + Alo*Bhi + Ahi*Blo, fp32 accumulate.
    // W2 staged per 16-k tile (bf16 hi/lo, n-major), software-pipelined LDG.
    {
        int wid = tid >> 5, lane = tid & 31;
        int m0 = (wid >> 1) * 16;
        int nbase = (wid & 1) * 128;
        float c[16][4];
#pragma unroll
        for (int nt = 0; nt < 16; nt++)
#pragma unroll
            for (int e = 0; e < 4; e++) c[nt][e] = 0.f;

        // LDSM lane addresses (bytes)
        unsigned a_hi = su32(h1hi) +
                        ((m0 + (lane & 15)) * HB + (lane >> 4) * 8) * 2;
        unsigned a_lo = a_hi + H1_ELEMS * 2;
        unsigned b_hi = su32(wt_hi) +
                        ((nbase + (lane & 7) + ((lane >> 4) << 3)) * WB +
                         ((lane >> 3) & 1) * 8) * 2;
        unsigned b_lo = b_hi + WT_ELEMS * 2;
        unsigned wt_hi_st = su32(wt_hi) + tid * (WB * 2);
        unsigned wt_lo_st = wt_hi_st + WT_ELEMS * 2;

        for (int kt = 0; kt < 16; kt++) {
            // stage kt: convert wreg -> bf16x2 pairs, STS.32
#pragma unroll
            for (int r2 = 0; r2 < 8; r2++) {
                float w0 = wreg[2 * r2], w1 = wreg[2 * r2 + 1];
                __nv_bfloat16 h0 = __float2bfloat16(w0);
                __nv_bfloat16 h1v = __float2bfloat16(w1);
                __nv_bfloat162 hp; hp.x = h0; hp.y = h1v;
                __nv_bfloat162 lp;
                lp.x = __float2bfloat16(w0 - __bfloat162float(h0));
                lp.y = __float2bfloat16(w1 - __bfloat162float(h1v));
                asm volatile("st.shared.b32 [%0], %1;" ::
                             "r"(wt_hi_st + 4 * r2),
                             "r"(*(unsigned*)&hp) : "memory");
                asm volatile("st.shared.b32 [%0], %1;" ::
                             "r"(wt_lo_st + 4 * r2),
                             "r"(*(unsigned*)&lp) : "memory");
            }
            __syncthreads();
            // prefetch next stage while MMAs run
            if (kt < 15) {
#pragma unroll
                for (int r = 0; r < 16; r++)
                    wreg[r] = W2[((kt + 1) * 16 + r) * 256 + tid];
            }
            unsigned ahi[4], alo[4];
            ldsm_x4(ahi, a_hi + kt * 32);
            ldsm_x4(alo, a_lo + kt * 32);
#pragma unroll
            for (int tp = 0; tp < 8; tp++) {
                unsigned bh[4], bl[4];
                ldsm_x4(bh, b_hi + tp * (16 * WB * 2));
                ldsm_x4(bl, b_lo + tp * (16 * WB * 2));
                mma_bf16(c[2 * tp],     ahi, bh);
                mma_bf16(c[2 * tp],     alo, bh);
                mma_bf16(c[2 * tp],     ahi, bl);
                mma_bf16(c[2 * tp + 1], ahi, bh + 2);
                mma_bf16(c[2 * tp + 1], alo, bh + 2);
                mma_bf16(c[2 * tp + 1], ahi, bl + 2);
            }
            __syncthreads();   // reads done before next stage overwrites wt
        }
        // epilogue: bias + relu -> hs2 fp32 (aliases h1 region; fenced above)
        float* hs2 = buf;  // [64][H2P]
        int g = lane >> 2, t = lane & 3;
        int ra = m0 + g, rb = ra + 8;
#pragma unroll
        for (int nt = 0; nt < 16; nt++) {
            int col = nbase + 8 * nt + 2 * t;
            float2 bv = *(const float2*)(b2 + col);
            float2 s0 = {fmaxf(c[nt][0] + bv.x, 0.f),
                         fmaxf(c[nt][1] + bv.y, 0.f)};
            float2 s1 = {fmaxf(c[nt][2] + bv.x, 0.f),
                         fmaxf(c[nt][3] + bv.y, 0.f)};
            *(float2*)(hs2 + ra * H2P + col) = s0;
            *(float2*)(hs2 + rb * H2P + col) = s1;
        }
    }
    __syncthreads();

    // ---------------- phase 3: heads + rsample + log_prob -------------------
    // 4 threads/row, 64 k each, shfl-reduce in 4-lane groups.
    {
        int row = tid >> 2, sub = tid & 3;
        const float* hrow = buf + row * H2P + sub * 64;
        const float* wm = Wmu + sub * 128;
        const float* wl = Wls + sub * 128;
        float m0 = 0.f, m1 = 0.f, l0 = 0.f, l1 = 0.f;
#pragma unroll 8
        for (int k = 0; k < 64; k++) {
            float hv = hrow[k];
            float2 a = *(const float2*)(wm + 2 * k);
            float2 c = *(const float2*)(wl + 2 * k);
            m0 = fmaf(hv, a.x, m0);
            m1 = fmaf(hv, a.y, m1);
            l0 = fmaf(hv, c.x, l0);
            l1 = fmaf(hv, c.y, l1);
        }
#pragma unroll
        for (int d = 2; d > 0; d >>= 1) {
            m0 += __shfl_down_sync(0xFFFFFFFFu, m0, d);
            m1 += __shfl_down_sync(0xFFFFFFFFu, m1, d);
            l0 += __shfl_down_sync(0xFFFFFFFFu, l0, d);
            l1 += __shfl_down_sync(0xFFFFFFFFu, l1, d);
        }
        if (sub == 0) {
            m0 += bmu[0]; m1 += bmu[1]; l0 += bls[0]; l1 += bls[1];
            int grow = bb * TTK + r0 + row;
            float mu[2]  = {tanh_acc(m0), tanh_acc(m1)};
            float lsr[2] = {l0, l1};
            float lp = 0.0f;
#pragma unroll
            for (int o2 = 0; o2 < 2; o2++) {
                // log_std = -20 + 0.5*(2-(-20))*(tanh+1) = -20 + 11*(tanh+1)
                float ls = -20.0f + 11.0f * (tanh_acc(lsr[o2]) + 1.0f);
                float sd = __expf(ls);
                float nz = noise[grow * 2 + o2];
                float z  = mu[o2] + sd * nz;
                float a  = tanh_acc(z);
                out_action[grow * 2 + o2] = a;
                lp += (-0.5f * nz * nz - ls - 0.9189385332046727f)
                      - __logf(1.0f - a * a + 1e-7f);
            }
            out_logp[grow] = lp;
        }
    }
}

// ---------------------------------------------------------------------------
extern "C" void kernel_launch(void* const* d_in, const int* in_sizes, int n_in,
                              void* d_out, int out_size) {
    const float* state = (const float*)d_in[0];
    const float* noise = (const float*)d_in[1];
    const float* Wq  = (const float*)d_in[2];
    const float* Wk  = (const float*)d_in[3];
    const float* Wv  = (const float*)d_in[4];
    const float* W1  = (const float*)d_in[5];
    const float* b1  = (const float*)d_in[6];
    const float* W2  = (const float*)d_in[7];
    const float* b2  = (const float*)d_in[8];
    const float* Wmu = (const float*)d_in[9];
    const float* bmu = (const float*)d_in[10];
    const float* Wls = (const float*)d_in[11];
    const float* bls = (const float*)d_in[12];
    float* out = (float*)d_out;

    cudaFuncSetAttribute(actor_kernel,
                         cudaFuncAttributeMaxDynamicSharedMemorySize, SMEM_BYTES);
    actor_kernel<<<256, 256, SMEM_BYTES>>>(
        state, noise, Wq, Wk, Wv, W1, b1, W2, b2, Wmu, bmu, Wls, bls,
        out /*action*/, out + 32768 /*log_prob*/);
}